// round 9
// baseline (speedup 1.0000x reference)
#include <cuda_runtime.h>
#include <cuda_bf16.h>
#include <mma.h>
#include <math.h>

using namespace nvcuda;

#define NN 100000
#define EE 1600000
#define HH 128
#define NPAD (NN + 128)
#define SCAN_B 512
#define SCAN_NB ((NN + SCAN_B - 1) / SCAN_B)   // 196

// ---------------- scratch ----------------------------------------------------
__device__ float4 g_bufA4[(size_t)NPAD * HH / 4];
__device__ float4 g_bufB4[(size_t)NPAD * HH / 4];
__device__ float4 g_res4 [(size_t)NPAD * HH / 4];
__device__ float  g_dis [NN];
__device__ float  g_deg [NN];
__device__ float  g_s   [NN];
__device__ int    g_cnt [NN];
__device__ int    g_cur [NN];
__device__ int    g_partial[NN];
__device__ int    g_bsum[SCAN_B];
__device__ int    g_rowptr[NN + 1];
__device__ int    g_srcs[EE];
__device__ float  g_wS [EE];

#define SEL_A 0
#define SEL_B 1
#define SEL_R 2
__device__ __forceinline__ float* pick(int sel) {
    return sel == SEL_A ? (float*)g_bufA4
         : (sel == SEL_B ? (float*)g_bufB4 : (float*)g_res4);
}

// ---------------- CSR build --------------------------------------------------
__global__ void k_init(int n) {
    int i = blockIdx.x * blockDim.x + threadIdx.x;
    if (i < n) { g_deg[i] = 1.0f; g_cnt[i] = 0; g_cur[i] = 0; }
}

__global__ void k_edge_count(const int* __restrict__ ei,
                             const float* __restrict__ ew, int E) {
    int e = blockIdx.x * blockDim.x + threadIdx.x;
    if (e < E) {
        int c = ei[E + e];
        atomicAdd(&g_deg[c], ew[e]);
        atomicAdd(&g_cnt[c], 1);
    }
}

__global__ void k_scan1(int n) {           // grid = SCAN_NB, block = SCAN_B
    __shared__ int sh[SCAN_B];
    int i = blockIdx.x * SCAN_B + threadIdx.x;
    int v = (i < n) ? g_cnt[i] : 0;
    sh[threadIdx.x] = v;
    __syncthreads();
    for (int o = 1; o < SCAN_B; o <<= 1) {
        int t = (threadIdx.x >= o) ? sh[threadIdx.x - o] : 0;
        __syncthreads();
        sh[threadIdx.x] += t;
        __syncthreads();
    }
    if (i < n) g_partial[i] = sh[threadIdx.x] - v;          // exclusive
    if (threadIdx.x == SCAN_B - 1) g_bsum[blockIdx.x] = sh[threadIdx.x];
}

__global__ void k_scan2(int nb) {          // 1 block of SCAN_B
    __shared__ int sh[SCAN_B];
    int v = (threadIdx.x < nb) ? g_bsum[threadIdx.x] : 0;
    sh[threadIdx.x] = v;
    __syncthreads();
    for (int o = 1; o < SCAN_B; o <<= 1) {
        int t = (threadIdx.x >= o) ? sh[threadIdx.x - o] : 0;
        __syncthreads();
        sh[threadIdx.x] += t;
        __syncthreads();
    }
    if (threadIdx.x < nb) g_bsum[threadIdx.x] = sh[threadIdx.x] - v;  // exclusive
}

__global__ void k_scan3(int n, int E) {    // rowptr assembly + dis = rsqrt(deg)
    int i = blockIdx.x * blockDim.x + threadIdx.x;
    if (i < n) {
        g_rowptr[i] = g_partial[i] + g_bsum[i / SCAN_B];
        g_dis[i] = rsqrtf(g_deg[i]);
    }
    if (i == 0) g_rowptr[n] = E;
}

__global__ void k_fillcsr(const int* __restrict__ ei,
                          const float* __restrict__ ew, int E) {
    int e = blockIdx.x * blockDim.x + threadIdx.x;
    if (e < E) {
        int r = ei[e];
        int c = ei[E + e];
        int pos = g_rowptr[c] + atomicAdd(&g_cur[c], 1);
        g_srcs[pos] = r;
        g_wS[pos]   = g_dis[r] * ew[e] * g_dis[c];
    }
}

// ---------------- bf16x3 tensor-core GEMM: C[M,128] = A[M,K] @ B[K,128] ------
#define ASTR 40
#define BSTR 136
__global__ __launch_bounds__(256)
void gemm_bf16x3(const float* __restrict__ A_ext, int selA,
                 const float* __restrict__ B, int selC, int M, int K) {
    const float* A = (selA < 0) ? A_ext : pick(selA);
    float* C = pick(selC);

    __shared__ __nv_bfloat16 AsH[128][ASTR], AsL[128][ASTR];
    __shared__ __nv_bfloat16 BsH[32][BSTR],  BsL[32][BSTR];

    int tid = threadIdx.x;
    int wid = tid >> 5;
    int warpM = wid >> 2;     // 0..1 -> 64 rows
    int warpN = wid & 3;      // 0..3 -> 32 cols
    int row0 = blockIdx.x * 128;

    wmma::fragment<wmma::accumulator, 16, 16, 16, float> acc[4][2];
    #pragma unroll
    for (int i = 0; i < 4; i++)
        #pragma unroll
        for (int j = 0; j < 2; j++) wmma::fill_fragment(acc[i][j], 0.0f);

    int ar = tid >> 3;            // 0..31
    int ac = (tid & 7) * 4;       // 0..28
    int br = tid >> 6;            // 0..3
    int bc = (tid & 63) * 2;      // 0..126

    float4 avr[4];
    float2 bvr[8];

    #pragma unroll
    for (int p = 0; p < 4; p++) {
        int gr = row0 + ar + p * 32;
        avr[p] = make_float4(0.f, 0.f, 0.f, 0.f);
        if (gr < M) avr[p] = *(const float4*)(A + (size_t)gr * K + ac);
    }
    #pragma unroll
    for (int p = 0; p < 8; p++)
        bvr[p] = *(const float2*)(B + (size_t)(br + p * 4) * 128 + bc);

    int ntiles = K >> 5;
    for (int t = 0; t < ntiles; t++) {
        #pragma unroll
        for (int p = 0; p < 4; p++) {
            int r = ar + p * 32;
            float4 v = avr[p];
            __nv_bfloat16 hx = __float2bfloat16(v.x);
            __nv_bfloat16 hy = __float2bfloat16(v.y);
            __nv_bfloat16 hz = __float2bfloat16(v.z);
            __nv_bfloat16 hw = __float2bfloat16(v.w);
            AsH[r][ac+0] = hx; AsL[r][ac+0] = __float2bfloat16(v.x - __bfloat162float(hx));
            AsH[r][ac+1] = hy; AsL[r][ac+1] = __float2bfloat16(v.y - __bfloat162float(hy));
            AsH[r][ac+2] = hz; AsL[r][ac+2] = __float2bfloat16(v.z - __bfloat162float(hz));
            AsH[r][ac+3] = hw; AsL[r][ac+3] = __float2bfloat16(v.w - __bfloat162float(hw));
        }
        #pragma unroll
        for (int p = 0; p < 8; p++) {
            int r = br + p * 4;
            float2 v = bvr[p];
            __nv_bfloat16 hx = __float2bfloat16(v.x);
            __nv_bfloat16 hy = __float2bfloat16(v.y);
            BsH[r][bc+0] = hx; BsL[r][bc+0] = __float2bfloat16(v.x - __bfloat162float(hx));
            BsH[r][bc+1] = hy; BsL[r][bc+1] = __float2bfloat16(v.y - __bfloat162float(hy));
        }
        __syncthreads();

        if (t + 1 < ntiles) {
            int k0 = (t + 1) << 5;
            #pragma unroll
            for (int p = 0; p < 4; p++) {
                int gr = row0 + ar + p * 32;
                avr[p] = make_float4(0.f, 0.f, 0.f, 0.f);
                if (gr < M) avr[p] = *(const float4*)(A + (size_t)gr * K + k0 + ac);
            }
            #pragma unroll
            for (int p = 0; p < 8; p++)
                bvr[p] = *(const float2*)(B + (size_t)(k0 + br + p * 4) * 128 + bc);
        }

        #pragma unroll
        for (int kk = 0; kk < 32; kk += 16) {
            wmma::fragment<wmma::matrix_a, 16, 16, 16, __nv_bfloat16, wmma::row_major> ah[4], al[4];
            wmma::fragment<wmma::matrix_b, 16, 16, 16, __nv_bfloat16, wmma::row_major> bh[2], bl[2];
            #pragma unroll
            for (int i = 0; i < 4; i++) {
                wmma::load_matrix_sync(ah[i], &AsH[warpM * 64 + i * 16][kk], ASTR);
                wmma::load_matrix_sync(al[i], &AsL[warpM * 64 + i * 16][kk], ASTR);
            }
            #pragma unroll
            for (int j = 0; j < 2; j++) {
                wmma::load_matrix_sync(bh[j], &BsH[kk][warpN * 32 + j * 16], BSTR);
                wmma::load_matrix_sync(bl[j], &BsL[kk][warpN * 32 + j * 16], BSTR);
            }
            #pragma unroll
            for (int i = 0; i < 4; i++)
                #pragma unroll
                for (int j = 0; j < 2; j++) {
                    wmma::mma_sync(acc[i][j], al[i], bh[j], acc[i][j]);
                    wmma::mma_sync(acc[i][j], ah[i], bl[j], acc[i][j]);
                    wmma::mma_sync(acc[i][j], ah[i], bh[j], acc[i][j]);
                }
        }
        __syncthreads();
    }

    #pragma unroll
    for (int i = 0; i < 4; i++)
        #pragma unroll
        for (int j = 0; j < 2; j++) {
            float* cp = C + (size_t)(row0 + warpM * 64 + i * 16) * 128 + warpN * 32 + j * 16;
            wmma::store_matrix_sync(cp, acc[i][j], 128, wmma::mem_row_major);
        }
}

// ---------------- fused CSR gather + selfloop + bias (+res) + BN + ReLU ------
// One warp per node; unroll 8 (32 float4 loads in flight per warp).
__global__ __launch_bounds__(512)
void k_gather_ep(int selH, int selOut,
                 const float* __restrict__ bvec,
                 const float* __restrict__ g, const float* __restrict__ be,
                 const float* __restrict__ m, const float* __restrict__ v,
                 int selRes, const float* __restrict__ w3, int n) {
    int warp = (blockIdx.x * blockDim.x + threadIdx.x) >> 5;
    if (warp >= n) return;
    int lane = threadIdx.x & 31;
    const float* h = pick(selH);

    float d = g_dis[warp];
    float d2 = d * d;
    float4 p = *(const float4*)(h + (size_t)warp * 128 + lane * 4);
    float4 a;
    a.x = p.x * d2; a.y = p.y * d2; a.z = p.z * d2; a.w = p.w * d2;

    int beg = __ldg(&g_rowptr[warp]), end = __ldg(&g_rowptr[warp + 1]);
    int k = beg;
    for (; k + 7 < end; k += 8) {
        int   ri[8]; float wi[8];
        #pragma unroll
        for (int u = 0; u < 8; u++) { ri[u] = __ldg(&g_srcs[k + u]); wi[u] = __ldg(&g_wS[k + u]); }
        float4 hv[8];
        #pragma unroll
        for (int u = 0; u < 8; u++)
            hv[u] = *(const float4*)(h + (size_t)ri[u] * 128 + lane * 4);
        #pragma unroll
        for (int u = 0; u < 8; u++) {
            a.x += hv[u].x * wi[u];
            a.y += hv[u].y * wi[u];
            a.z += hv[u].z * wi[u];
            a.w += hv[u].w * wi[u];
        }
    }
    for (; k + 3 < end; k += 4) {
        int   ri[4]; float wi[4];
        #pragma unroll
        for (int u = 0; u < 4; u++) { ri[u] = __ldg(&g_srcs[k + u]); wi[u] = __ldg(&g_wS[k + u]); }
        float4 hv[4];
        #pragma unroll
        for (int u = 0; u < 4; u++)
            hv[u] = *(const float4*)(h + (size_t)ri[u] * 128 + lane * 4);
        #pragma unroll
        for (int u = 0; u < 4; u++) {
            a.x += hv[u].x * wi[u];
            a.y += hv[u].y * wi[u];
            a.z += hv[u].z * wi[u];
            a.w += hv[u].w * wi[u];
        }
    }
    for (; k < end; k++) {
        int   r0 = __ldg(&g_srcs[k]);
        float w0 = __ldg(&g_wS[k]);
        float4 h0 = *(const float4*)(h + (size_t)r0 * 128 + lane * 4);
        a.x += h0.x * w0; a.y += h0.y * w0; a.z += h0.z * w0; a.w += h0.w * w0;
    }

    int j4 = lane * 4;
    float4 bv = *(const float4*)(bvec + j4);
    a.x += bv.x; a.y += bv.y; a.z += bv.z; a.w += bv.w;
    if (selRes >= 0) {
        float4 rr = *(const float4*)(pick(selRes) + (size_t)warp * 128 + j4);
        a.x += rr.x; a.y += rr.y; a.z += rr.z; a.w += rr.w;
    }
    float4 gv = *(const float4*)(g + j4);
    float4 vv = *(const float4*)(v + j4);
    float4 mv = *(const float4*)(m + j4);
    float4 bb = *(const float4*)(be + j4);
    float4 o;
    o.x = fmaxf((a.x - mv.x) * (gv.x * rsqrtf(vv.x + 1e-5f)) + bb.x, 0.f);
    o.y = fmaxf((a.y - mv.y) * (gv.y * rsqrtf(vv.y + 1e-5f)) + bb.y, 0.f);
    o.z = fmaxf((a.z - mv.z) * (gv.z * rsqrtf(vv.z + 1e-5f)) + bb.z, 0.f);
    o.w = fmaxf((a.w - mv.w) * (gv.w * rsqrtf(vv.w + 1e-5f)) + bb.w, 0.f);
    *(float4*)(pick(selOut) + (size_t)warp * 128 + j4) = o;

    if (w3) {   // fused GEMV: s = o . w3
        float4 wv = ((const float4*)w3)[lane];
        float s = o.x * wv.x + o.y * wv.y + o.z * wv.z + o.w * wv.w;
        #pragma unroll
        for (int off = 16; off > 0; off >>= 1) s += __shfl_down_sync(0xffffffffu, s, off);
        if (lane == 0) g_s[warp] = s;
    }
}

// ---------------- layer 3: warp-per-node scalar CSR gather -------------------
__global__ __launch_bounds__(512)
void k_out(const float* __restrict__ b3, float* __restrict__ out, int n) {
    int warp = (blockIdx.x * blockDim.x + threadIdx.x) >> 5;
    if (warp >= n) return;
    int lane = threadIdx.x & 31;
    int beg = __ldg(&g_rowptr[warp]), end = __ldg(&g_rowptr[warp + 1]);
    float acc = 0.0f;
    for (int k = beg + lane; k < end; k += 32)
        acc += g_s[__ldg(&g_srcs[k])] * __ldg(&g_wS[k]);
    #pragma unroll
    for (int off = 16; off > 0; off >>= 1) acc += __shfl_down_sync(0xffffffffu, acc, off);
    if (lane == 0) {
        float d = g_dis[warp];
        out[warp] = b3[0] + g_s[warp] * d * d + acc;
    }
}

// ---------------- launch ----------------------------------------------------
extern "C" void kernel_launch(void* const* d_in, const int* in_sizes, int n_in,
                              void* d_out, int out_size) {
    const float* x    = (const float*)d_in[0];
    const int*   ei   = (const int*)d_in[1];     // int32 (JAX x64 disabled)
    const float* ew   = (const float*)d_in[2];
    const float* W1   = (const float*)d_in[3];
    const float* b1   = (const float*)d_in[4];
    const float* W2   = (const float*)d_in[5];
    const float* b2   = (const float*)d_in[6];
    const float* W3   = (const float*)d_in[7];
    const float* b3   = (const float*)d_in[8];
    const float* Wres = (const float*)d_in[9];
    const float* g1   = (const float*)d_in[10];
    const float* be1  = (const float*)d_in[11];
    const float* m1   = (const float*)d_in[12];
    const float* v1   = (const float*)d_in[13];
    const float* g2   = (const float*)d_in[14];
    const float* be2  = (const float*)d_in[15];
    const float* m2   = (const float*)d_in[16];
    const float* v2   = (const float*)d_in[17];
    float* out = (float*)d_out;
    (void)n_in;

    const int N  = out_size;          // 100000
    const int E  = in_sizes[1] / 2;   // 1600000
    const int K1 = in_sizes[0] / N;   // 256

    const int T = 256;
    int nb_N    = (N + T - 1) / T;
    int nb_E    = (E + T - 1) / T;
    int nb_M    = (N + 127) / 128;
    int nb_warp512 = (N * 32 + 511) / 512;

    static cudaStream_t s_csr = nullptr, s_g1 = nullptr, s_gr = nullptr;
    static cudaEvent_t  e_fork = nullptr, e_csr = nullptr, e_g1 = nullptr, e_gr = nullptr;
    if (!s_csr) {
        cudaStreamCreateWithFlags(&s_csr, cudaStreamNonBlocking);
        cudaStreamCreateWithFlags(&s_g1,  cudaStreamNonBlocking);
        cudaStreamCreateWithFlags(&s_gr,  cudaStreamNonBlocking);
        cudaEventCreateWithFlags(&e_fork, cudaEventDisableTiming);
        cudaEventCreateWithFlags(&e_csr,  cudaEventDisableTiming);
        cudaEventCreateWithFlags(&e_g1,   cudaEventDisableTiming);
        cudaEventCreateWithFlags(&e_gr,   cudaEventDisableTiming);
    }

    // fork
    cudaEventRecord(e_fork, 0);
    cudaStreamWaitEvent(s_csr, e_fork, 0);
    cudaStreamWaitEvent(s_g1,  e_fork, 0);
    cudaStreamWaitEvent(s_gr,  e_fork, 0);

    // --- CSR build + normalization (stream s_csr) ---
    k_init<<<nb_N, T, 0, s_csr>>>(N);
    k_edge_count<<<nb_E, T, 0, s_csr>>>(ei, ew, E);
    k_scan1<<<SCAN_NB, SCAN_B, 0, s_csr>>>(N);
    k_scan2<<<1, SCAN_B, 0, s_csr>>>(SCAN_NB);
    k_scan3<<<nb_N, T, 0, s_csr>>>(N, E);
    k_fillcsr<<<nb_E, T, 0, s_csr>>>(ei, ew, E);
    cudaEventRecord(e_csr, s_csr);

    // --- layer 1 GEMMs (parallel streams) ---
    gemm_bf16x3<<<nb_M, T, 0, s_g1>>>(x, -1, W1,   SEL_A, N, K1);
    cudaEventRecord(e_g1, s_g1);
    gemm_bf16x3<<<nb_M, T, 0, s_gr>>>(x, -1, Wres, SEL_R, N, K1);
    cudaEventRecord(e_gr, s_gr);

    // join CSR + GEMM1 before gather1
    cudaStreamWaitEvent(0, e_csr, 0);
    cudaStreamWaitEvent(0, e_g1, 0);

    // --- propagate 1 (gather, fused epilogue) ---
    k_gather_ep<<<nb_warp512, 512>>>(SEL_A, SEL_B, b1, g1, be1, m1, v1, -1, nullptr, N);

    // --- layer 2: h2_pre = h1@W2 ---
    gemm_bf16x3<<<nb_M, T>>>(nullptr, SEL_B, W2, SEL_A, N, 128);

    // join GEMMres before gather2 (its only consumer)
    cudaStreamWaitEvent(0, e_gr, 0);

    // --- propagate 2 (gather, fused epilogue + residual + GEMV w3) ---
    k_gather_ep<<<nb_warp512, 512>>>(SEL_A, SEL_B, b2, g2, be2, m2, v2, SEL_R, W3, N);

    // --- layer 3: scalar gather ---
    k_out<<<nb_warp512, 512>>>(b3, out, N);
}